// round 12
// baseline (speedup 1.0000x reference)
#include <cuda_runtime.h>
#include <cuda_fp16.h>
#include <math.h>

// Problem constants
static constexpr int   N_NODES  = 200000;
static constexpr int   N_USERS  = 100000;
static constexpr int   DIM      = 64;
static constexpr int   LAYERS   = 3;
static constexpr int   E_EDGES  = 3000000;
static constexpr int   N_LINK   = 100000;
static constexpr int   EMB_COLS = (LAYERS + 1) * DIM;             // 256
static constexpr int   CSR_CAP  = E_EDGES + 16 * N_NODES + 64;    // 16-padded capacity

// ---------------------------------------------------------------------------
// Scratch. Feature tables have a ZERO GUARD ROW at index 0 (node v -> row v+1).
// Guard rows are never written (zero from .bss forever). CSR entries store
// (src+1); padding entries are 0 and gather the guard row (adds 0.0, L1-hot).
// deg/csr/totals are re-zeroed by k_tail at the END of each call.
//
// fp16 GATHER TABLES: convs gather dense __half rows (128B) from g_hxs/g_hxt,
// accumulate packed with HADD2 (<=4-term fp16 chains), flush to fp32.
// GEMM + pred remain fp32.
// ---------------------------------------------------------------------------
__device__ int    g_deg_s[N_NODES],  g_deg_t[N_NODES];
__device__ int2   g_seg_s[N_NODES],  g_seg_t[N_NODES];   // {start, deg}
__device__ int    g_cur_s[N_NODES],  g_cur_t[N_NODES];
__device__ int    g_tot_s,           g_tot_t;
__device__ int    g_csr_s[CSR_CAP],  g_csr_t[CSR_CAP];
__device__ float  g_invdeg_s[N_NODES], g_invdeg_t[N_NODES];
__device__ float  g_means[(size_t)(N_NODES + 1) * DIM];       // +guard (fp32)
__device__ float  g_meant[(size_t)(N_NODES + 1) * DIM];       // +guard (fp32)
__device__ __half g_hxs [(size_t)(N_NODES + 1) * DIM];        // fp16 gather (source)
__device__ __half g_hxt [(size_t)(N_NODES + 1) * DIM];        // fp16 gather (target)
__device__ float  g_embs [(size_t)(N_NODES + 1) * EMB_COLS];  // fp32 [emb|x1|x2|x3]

// ---------------------------------------------------------------------------
// (1) Histogram degrees for both graphs (deg arrays are pre-zeroed).
// ---------------------------------------------------------------------------
__global__ void k_hist(const int* __restrict__ s_dst, const int* __restrict__ t_dst) {
    int e = blockIdx.x * blockDim.x + threadIdx.x;
    if (e < E_EDGES) {
        atomicAdd(&g_deg_s[s_dst[e]], 1);
        atomicAdd(&g_deg_t[t_dst[e]], 1);
    }
}

// ---------------------------------------------------------------------------
// (2) Claim 16-padded CSR segments (block-aggregated scan, 1 atomic per
// block per graph). Also: invdeg; copy emb into g_embs block 0 (fp32) and
// into g_hxs (fp16 layer-0 gather table, shared by both graphs).
// ---------------------------------------------------------------------------
__global__ void k_offsets(const float4* __restrict__ emb4) {
    __shared__ int sh_s[256], sh_t[256];
    __shared__ int base_s, base_t;
    int t = threadIdx.x;
    int i = blockIdx.x * 256 + t;

    int ds = 0, dt = 0;
    if (i < N_NODES) { ds = g_deg_s[i]; dt = g_deg_t[i]; }
    int ps = (ds + 15) & ~15, pt = (dt + 15) & ~15;
    sh_s[t] = ps; sh_t[t] = pt;
    __syncthreads();
    #pragma unroll
    for (int off = 1; off < 256; off <<= 1) {
        int a = (t >= off) ? sh_s[t - off] : 0;
        int b = (t >= off) ? sh_t[t - off] : 0;
        __syncthreads();
        sh_s[t] += a; sh_t[t] += b;
        __syncthreads();
    }
    if (t == 255) {
        base_s = atomicAdd(&g_tot_s, sh_s[255]);
        base_t = atomicAdd(&g_tot_t, sh_t[255]);
    }
    __syncthreads();
    if (i < N_NODES) {
        int rs = base_s + sh_s[t] - ps;
        int rt = base_t + sh_t[t] - pt;
        g_seg_s[i] = make_int2(rs, ds);  g_cur_s[i] = rs;
        g_seg_t[i] = make_int2(rt, dt);  g_cur_t[i] = rt;
        g_invdeg_s[i] = 1.f / fmaxf((float)ds, 1.f);
        g_invdeg_t[i] = 1.f / fmaxf((float)dt, 1.f);
    }
    // emb -> g_embs (fp32, rows 1..N) and g_hxs (fp16)
    const long NF4 = (long)N_NODES * (DIM / 4);
    long stride = (long)gridDim.x * blockDim.x;
    for (long j = (long)blockIdx.x * 256 + t; j < NF4; j += stride) {
        long v = j >> 4;
        int  d = (int)(j & 15);
        float4 f = emb4[j];
        reinterpret_cast<float4*>(g_embs)[(v + 1) * (EMB_COLS / 4) + d] = f;
        __half2* h2 = reinterpret_cast<__half2*>(g_hxs) + (v + 1) * (DIM / 2) + 2 * d;
        h2[0] = __floats2half2_rn(f.x, f.y);
        h2[1] = __floats2half2_rn(f.z, f.w);
    }
}

// ---------------------------------------------------------------------------
// (3) Fill CSR: store src+1 (0 is reserved for the zero guard row).
// ---------------------------------------------------------------------------
__global__ void k_fill(const int* __restrict__ s_src, const int* __restrict__ s_dst,
                       const int* __restrict__ t_src, const int* __restrict__ t_dst) {
    int e = blockIdx.x * blockDim.x + threadIdx.x;
    if (e < E_EDGES) {
        int ps = atomicAdd(&g_cur_s[s_dst[e]], 1);
        g_csr_s[ps] = s_src[e] + 1;
        int pt = atomicAdd(&g_cur_t[t_dst[e]], 1);
        g_csr_t[pt] = t_src[e] + 1;
    }
}

// ---------------------------------------------------------------------------
// (4..) fp16 gather conv with PACKED HADD2 accumulation.
// HALF-WARP per node; row = 64 halves = 128B; lane loads uint4 (8 halves),
// 8 lanes cover a row, 2 neighbors per round. Neighbors processed in
// subgroups of 4: fp16 half2 chains (<=4 terms) then one fp32 flush.
// Per 16 edges per lane: 8 LDG + 8 SHFL + 24 HADD2 + 8 cvt-pairs + 8 FADD.
// ---------------------------------------------------------------------------
__global__ void __launch_bounds__(256)
k_conv(const __half* __restrict__ x,
       const int2* __restrict__ seg, const float* __restrict__ invd,
       const int* __restrict__ csr, float* __restrict__ om, int nN) {
    int w = (blockIdx.x * blockDim.x + threadIdx.x) >> 5;
    if (w >= nN / 2) return;
    int      lane = threadIdx.x & 31;
    int      h    = lane >> 4;                      // half-warp id
    int      q    = lane & 15;                      // id within half-warp
    unsigned hm   = h ? 0xFFFF0000u : 0x0000FFFFu;
    int      v    = 2 * w + h;                      // 0-based node

    int2 sd    = __ldg(&seg[v]);                    // {start, deg}
    int  start = sd.x;
    int  p16   = (sd.y + 15) & ~15;

    int nb = q >> 3;                                // which of 2 neighbors/round
    int ck = q & 7;                                 // 16B chunk within row

    float acc[8] = {0.f, 0.f, 0.f, 0.f, 0.f, 0.f, 0.f, 0.f};

    for (int j0 = 0; j0 < p16; j0 += 16) {
        int idx = __ldg(&csr[start + j0 + q]);      // 16 entries per half-warp
        #pragma unroll
        for (int g = 0; g < 2; g++) {               // 2 subgroups x 4 rounds
            __half2 h0, h1, h2, h3;
            {
                int s = __shfl_sync(hm, idx, h * 16 + 8 * g + nb);
                uint4 u = __ldg(reinterpret_cast<const uint4*>(
                                    x + (size_t)s * DIM) + ck);
                h0 = *reinterpret_cast<const __half2*>(&u.x);
                h1 = *reinterpret_cast<const __half2*>(&u.y);
                h2 = *reinterpret_cast<const __half2*>(&u.z);
                h3 = *reinterpret_cast<const __half2*>(&u.w);
            }
            #pragma unroll
            for (int r = 1; r < 4; r++) {
                int s = __shfl_sync(hm, idx, h * 16 + 8 * g + 2 * r + nb);
                uint4 u = __ldg(reinterpret_cast<const uint4*>(
                                    x + (size_t)s * DIM) + ck);
                h0 = __hadd2(h0, *reinterpret_cast<const __half2*>(&u.x));
                h1 = __hadd2(h1, *reinterpret_cast<const __half2*>(&u.y));
                h2 = __hadd2(h2, *reinterpret_cast<const __half2*>(&u.z));
                h3 = __hadd2(h3, *reinterpret_cast<const __half2*>(&u.w));
            }
            float2 f;
            f = __half22float2(h0); acc[0] += f.x; acc[1] += f.y;
            f = __half22float2(h1); acc[2] += f.x; acc[3] += f.y;
            f = __half22float2(h2); acc[4] += f.x; acc[5] += f.y;
            f = __half22float2(h3); acc[6] += f.x; acc[7] += f.y;
        }
    }

    // fold the two neighbor classes (q and q+8); valid in lanes with nb==0
    #pragma unroll
    for (int i = 0; i < 8; i++)
        acc[i] += __shfl_down_sync(hm, acc[i], 8);

    if (nb == 0) {                                  // lanes q=0..7 of each half
        float iv = invd[v];
        float4 o0 = make_float4(acc[0] * iv, acc[1] * iv, acc[2] * iv, acc[3] * iv);
        float4 o1 = make_float4(acc[4] * iv, acc[5] * iv, acc[6] * iv, acc[7] * iv);
        float4* row = reinterpret_cast<float4*>(om + (size_t)(v + 1) * DIM);
        row[2 * ck]     = o0;                       // cols 8ck .. 8ck+7
        row[2 * ck + 1] = o1;
    }
}

// ---------------------------------------------------------------------------
// Combine: users get mix GEMM ue=[ms|mt]@W^T+b (fp32, float4-packed smem W).
// Writes fp32 source slice into g_embs(layer+1); fp16 copies into the next
// layer's gather tables g_hxs / g_hxt (skipped on the last layer).
// ---------------------------------------------------------------------------
__global__ void __launch_bounds__(256)
k_combine(const float* __restrict__ mix_w, const float* __restrict__ mix_b,
          int layer, int write_next) {
    // WT4[k2*32 + ln] = { W[ln][2k2], W[ln+32][2k2], W[ln][2k2+1], W[ln+32][2k2+1] }
    __shared__ float4 WT4[64 * 32];    // 32 KB
    __shared__ float  BB[64];

    const float* W = mix_w + (size_t)layer * 64 * 128;
    for (int i = threadIdx.x; i < 64 * 32; i += blockDim.x) {
        int k2 = i >> 5, ln = i & 31;
        WT4[i] = make_float4(W[ln * 128 + 2 * k2],     W[(ln + 32) * 128 + 2 * k2],
                             W[ln * 128 + 2 * k2 + 1], W[(ln + 32) * 128 + 2 * k2 + 1]);
    }
    if (threadIdx.x < 64) BB[threadIdx.x] = mix_b[layer * 64 + threadIdx.x];
    __syncthreads();

    int lane = threadIdx.x & 31;
    int warp = threadIdx.x >> 5;
    int wpb  = blockDim.x >> 5;

    for (int v = blockIdx.x * wpb + warp; v < N_NODES; v += gridDim.x * wpb) {
        size_t base = (size_t)(v + 1) * DIM;

        float ms0 = g_means[base + lane];
        float ms1 = g_means[base + 32 + lane];
        float mt0 = g_meant[base + lane];
        float mt1 = g_meant[base + 32 + lane];

        float o0, o1, t0, t1;
        if (v < N_USERS) {
            float a0 = BB[lane], a1 = BB[lane + 32];
            #pragma unroll
            for (int k2 = 0; k2 < 16; k2++) {
                float m0 = __shfl_sync(0xffffffffu, ms0, 2 * k2);
                float m1 = __shfl_sync(0xffffffffu, ms0, 2 * k2 + 1);
                float4 qv = WT4[k2 * 32 + lane];
                a0 += m0 * qv.x + m1 * qv.z;
                a1 += m0 * qv.y + m1 * qv.w;
            }
            #pragma unroll
            for (int k2 = 0; k2 < 16; k2++) {
                float m0 = __shfl_sync(0xffffffffu, ms1, 2 * k2);
                float m1 = __shfl_sync(0xffffffffu, ms1, 2 * k2 + 1);
                float4 qv = WT4[(16 + k2) * 32 + lane];
                a0 += m0 * qv.x + m1 * qv.z;
                a1 += m0 * qv.y + m1 * qv.w;
            }
            #pragma unroll
            for (int k2 = 0; k2 < 16; k2++) {
                float m0 = __shfl_sync(0xffffffffu, mt0, 2 * k2);
                float m1 = __shfl_sync(0xffffffffu, mt0, 2 * k2 + 1);
                float4 qv = WT4[(32 + k2) * 32 + lane];
                a0 += m0 * qv.x + m1 * qv.z;
                a1 += m0 * qv.y + m1 * qv.w;
            }
            #pragma unroll
            for (int k2 = 0; k2 < 16; k2++) {
                float m0 = __shfl_sync(0xffffffffu, mt1, 2 * k2);
                float m1 = __shfl_sync(0xffffffffu, mt1, 2 * k2 + 1);
                float4 qv = WT4[(48 + k2) * 32 + lane];
                a0 += m0 * qv.x + m1 * qv.z;
                a1 += m0 * qv.y + m1 * qv.w;
            }
            o0 = a0; o1 = a1; t0 = a0; t1 = a1;
        } else {
            o0 = ms0; o1 = ms1; t0 = mt0; t1 = mt1;
        }

        if (write_next) {
            __half* hs = g_hxs + base;
            hs[lane]      = __float2half_rn(o0);
            hs[lane + 32] = __float2half_rn(o1);
            __half* ht = g_hxt + base;
            ht[lane]      = __float2half_rn(t0);
            ht[lane + 32] = __float2half_rn(t1);
        }
        float* er = g_embs + (size_t)(v + 1) * EMB_COLS + (size_t)(layer + 1) * DIM;
        er[lane]      = o0;
        er[lane + 32] = o1;
    }
}

// ---------------------------------------------------------------------------
// Prediction head: warp per link, float4 loads (1-based rows, fp32).
// ---------------------------------------------------------------------------
__global__ void k_pred(const int* __restrict__ link,
                       const float* __restrict__ pred_w,
                       const float* __restrict__ pred_b,
                       float* __restrict__ out) {
    __shared__ float4 pw4[128];                       // 512 floats
    for (int i = threadIdx.x; i < 128; i += blockDim.x)
        pw4[i] = reinterpret_cast<const float4*>(pred_w)[i];
    __syncthreads();

    int lane = threadIdx.x & 31;
    int warp = threadIdx.x >> 5;
    int j = blockIdx.x * (blockDim.x >> 5) + warp;
    if (j >= N_LINK) return;

    int u  = __ldg(&link[j]) + 1;
    int it = __ldg(&link[N_LINK + j]) + 1;
    const float4* ue4 = reinterpret_cast<const float4*>(g_embs + (size_t)u  * EMB_COLS);
    const float4* ie4 = reinterpret_cast<const float4*>(g_embs + (size_t)it * EMB_COLS);

    float acc = 0.f;
    #pragma unroll
    for (int r = 0; r < 2; r++) {
        int idx = lane + r * 32;                      // 0..63
        float4 a = __ldg(&ue4[idx]);
        float4 w = pw4[idx];
        acc += a.x * w.x + a.y * w.y + a.z * w.z + a.w * w.w;
        float4 b = __ldg(&ie4[idx]);
        float4 w2 = pw4[64 + idx];
        acc += b.x * w2.x + b.y * w2.y + b.z * w2.z + b.w * w2.w;
    }

    #pragma unroll
    for (int o = 16; o > 0; o >>= 1) acc += __shfl_down_sync(0xffffffffu, acc, o);

    if (lane == 0) {
        float z = acc + pred_b[0];
        z = (z >= 0.f) ? z : 0.01f * z;
        out[j] = 1.f / (1.f + expf(-z));
    }
}

// ---------------------------------------------------------------------------
// Tail: restore the zero state (deg, totals, csr) for the next call.
// ---------------------------------------------------------------------------
__global__ void k_tail() {
    int stride = gridDim.x * blockDim.x;
    int t0 = blockIdx.x * blockDim.x + threadIdx.x;
    for (int i = t0; i < CSR_CAP; i += stride) { g_csr_s[i] = 0; g_csr_t[i] = 0; }
    for (int i = t0; i < N_NODES; i += stride) { g_deg_s[i] = 0; g_deg_t[i] = 0; }
    if (t0 == 0) { g_tot_s = 0; g_tot_t = 0; }
}

// ---------------------------------------------------------------------------
// Launch.
// ---------------------------------------------------------------------------
extern "C" void kernel_launch(void* const* d_in, const int* in_sizes, int n_in,
                              void* d_out, int out_size) {
    const int*   sei    = (const int*)  d_in[0];
    const int*   tei    = (const int*)  d_in[1];
    const int*   link   = (const int*)  d_in[2];
    const float* emb    = (const float*)d_in[3];
    const float* mix_w  = (const float*)d_in[4];
    const float* mix_b  = (const float*)d_in[5];
    const float* pred_w = (const float*)d_in[6];
    const float* pred_b = (const float*)d_in[7];
    float*       out    = (float*)d_out;

    const int* s_src = sei;
    const int* s_dst = sei + E_EDGES;
    const int* t_src = tei;
    const int* t_dst = tei + E_EDGES;

    k_hist   <<<(E_EDGES + 255) / 256, 256>>>(s_dst, t_dst);
    k_offsets<<<(N_NODES + 255) / 256, 256>>>(reinterpret_cast<const float4*>(emb));
    k_fill   <<<(E_EDGES + 255) / 256, 256>>>(s_src, s_dst, t_src, t_dst);

    for (int l = 0; l < LAYERS; l++) {
        // source conv gathers g_hxs (layer 0: fp16 emb; else fp16 combine out)
        k_conv<<<(N_NODES / 2 * 32 + 255) / 256, 256>>>(
            g_hxs, g_seg_s, g_invdeg_s, g_csr_s, g_means, N_NODES);
        // target conv: layer 0 gathers g_hxs (same emb table); else g_hxt.
        // Last layer: only user rows are ever consumed.
        const __half* xt = (l == 0) ? g_hxs : g_hxt;
        int           nT = (l == LAYERS - 1) ? N_USERS : N_NODES;
        k_conv<<<(nT / 2 * 32 + 255) / 256, 256>>>(
            xt, g_seg_t, g_invdeg_t, g_csr_t, g_meant, nT);

        k_combine<<<2960, 256>>>(mix_w, mix_b, l, l < LAYERS - 1 ? 1 : 0);
    }

    k_pred<<<(N_LINK + 7) / 8, 256>>>(link, pred_w, pred_b, out);
    k_tail<<<4096, 256>>>();
}

// round 13
// speedup vs baseline: 1.1903x; 1.1903x over previous
#include <cuda_runtime.h>
#include <math.h>

// Problem constants
static constexpr int   N_NODES  = 200000;
static constexpr int   N_USERS  = 100000;
static constexpr int   DIM      = 64;
static constexpr int   LAYERS   = 3;
static constexpr int   E_EDGES  = 3000000;
static constexpr int   N_LINK   = 100000;
static constexpr int   EMB_COLS = (LAYERS + 1) * DIM;             // 256
static constexpr int   CSR_CAP  = E_EDGES + 16 * N_NODES + 64;    // 16-padded capacity

// ---------------------------------------------------------------------------
// Scratch. Feature tables have a ZERO GUARD ROW at index 0 (node v -> row v+1).
// Guard rows are never written (zero from .bss forever). CSR entries store
// (src+1); padding entries are 0 and gather the guard row (adds 0.0, L1-hot).
// Padding slots are zeroed in k_offsets (disjoint from k_fill's data slots);
// k_tail re-zeroes only deg arrays + totals, so every call sees identical
// state and does identical work.
//
// L2 POLICY: gather tables g_xs / g_xt (dense fp32, 51MB each) are the ONLY
// data we want resident in L2. All big one-shot streams use evict-first
// (__ldcs / __stwt): CSR reads, mean stores+reads, g_embs slice stores.
// ---------------------------------------------------------------------------
__device__ int    g_deg_s[N_NODES],  g_deg_t[N_NODES];
__device__ int2   g_seg_s[N_NODES],  g_seg_t[N_NODES];   // {start, deg}
__device__ int    g_cur_s[N_NODES],  g_cur_t[N_NODES];
__device__ int    g_tot_s,           g_tot_t;
__device__ int    g_csr_s[CSR_CAP],  g_csr_t[CSR_CAP];
__device__ float  g_invdeg_s[N_NODES], g_invdeg_t[N_NODES];
__device__ float  g_means[(size_t)(N_NODES + 1) * DIM];       // +guard
__device__ float  g_meant[(size_t)(N_NODES + 1) * DIM];       // +guard
__device__ float  g_xs   [(size_t)(N_NODES + 1) * DIM];       // dense source gather
__device__ float  g_xt   [(size_t)(N_NODES + 1) * DIM];       // dense target gather
__device__ float  g_embs [(size_t)(N_NODES + 1) * EMB_COLS];  // [emb|x1|x2|x3] (pred)

// ---------------------------------------------------------------------------
// (1) Histogram degrees for both graphs (deg arrays are pre-zeroed).
// ---------------------------------------------------------------------------
__global__ void k_hist(const int* __restrict__ s_dst, const int* __restrict__ t_dst) {
    int e = blockIdx.x * blockDim.x + threadIdx.x;
    if (e < E_EDGES) {
        atomicAdd(&g_deg_s[__ldcs(&s_dst[e])], 1);
        atomicAdd(&g_deg_t[__ldcs(&t_dst[e])], 1);
    }
}

// ---------------------------------------------------------------------------
// (2) Claim 16-padded CSR segments (block-aggregated scan, 1 atomic per
// block per graph); zero THIS call's padding slots; invdeg; copy emb into
// g_embs block 0 (evict-first) and into g_xs (dense layer-0 gather table).
// ---------------------------------------------------------------------------
__global__ void k_offsets(const float4* __restrict__ emb4) {
    __shared__ int sh_s[256], sh_t[256];
    __shared__ int base_s, base_t;
    int t = threadIdx.x;
    int i = blockIdx.x * 256 + t;

    int ds = 0, dt = 0;
    if (i < N_NODES) { ds = g_deg_s[i]; dt = g_deg_t[i]; }
    int ps = (ds + 15) & ~15, pt = (dt + 15) & ~15;
    sh_s[t] = ps; sh_t[t] = pt;
    __syncthreads();
    #pragma unroll
    for (int off = 1; off < 256; off <<= 1) {
        int a = (t >= off) ? sh_s[t - off] : 0;
        int b = (t >= off) ? sh_t[t - off] : 0;
        __syncthreads();
        sh_s[t] += a; sh_t[t] += b;
        __syncthreads();
    }
    if (t == 255) {
        base_s = atomicAdd(&g_tot_s, sh_s[255]);
        base_t = atomicAdd(&g_tot_t, sh_t[255]);
    }
    __syncthreads();
    if (i < N_NODES) {
        int rs = base_s + sh_s[t] - ps;
        int rt = base_t + sh_t[t] - pt;
        g_seg_s[i] = make_int2(rs, ds);  g_cur_s[i] = rs;
        g_seg_t[i] = make_int2(rt, dt);  g_cur_t[i] = rt;
        g_invdeg_s[i] = 1.f / fmaxf((float)ds, 1.f);
        g_invdeg_t[i] = 1.f / fmaxf((float)dt, 1.f);
        // zero padding slots (k_fill writes only [start, start+deg))
        for (int p = ds; p < ps; p++) __stwt(&g_csr_s[rs + p], 0);
        for (int p = dt; p < pt; p++) __stwt(&g_csr_t[rt + p], 0);
    }
    // emb -> g_embs (evict-first; pred-only) and g_xs (L2-resident gather)
    const long NF4 = (long)N_NODES * (DIM / 4);
    long stride = (long)gridDim.x * blockDim.x;
    for (long j = (long)blockIdx.x * 256 + t; j < NF4; j += stride) {
        long v = j >> 4;
        int  d = (int)(j & 15);
        float4 f = __ldcs(&emb4[j]);
        __stwt(&reinterpret_cast<float4*>(g_embs)[(v + 1) * (EMB_COLS / 4) + d], f);
        reinterpret_cast<float4*>(g_xs)[(v + 1) * (DIM / 4) + d] = f;
    }
}

// ---------------------------------------------------------------------------
// (3) Fill CSR: store src+1 (0 is reserved for the zero guard row).
// ---------------------------------------------------------------------------
__global__ void k_fill(const int* __restrict__ s_src, const int* __restrict__ s_dst,
                       const int* __restrict__ t_src, const int* __restrict__ t_dst) {
    int e = blockIdx.x * blockDim.x + threadIdx.x;
    if (e < E_EDGES) {
        int ps = atomicAdd(&g_cur_s[__ldcs(&s_dst[e])], 1);
        __stwt(&g_csr_s[ps], __ldcs(&s_src[e]) + 1);
        int pt = atomicAdd(&g_cur_t[__ldcs(&t_dst[e])], 1);
        __stwt(&g_csr_t[pt], __ldcs(&t_src[e]) + 1);
    }
}

// ---------------------------------------------------------------------------
// (4..) Gather conv: HALF-WARP per node, float4 (LDG.128) lanes, dense
// fp32 tables (stride DIM). Rows padded to 16 -> most nodes are ONE
// branch-free group: 1 csr load (evict-first) + 16 independent gathers
// (default policy -> L2-resident). Mean store is evict-first.
// ---------------------------------------------------------------------------
__global__ void __launch_bounds__(256)
k_conv(const float* __restrict__ x,
       const int2* __restrict__ seg, const float* __restrict__ invd,
       const int* __restrict__ csr, float* __restrict__ om, int nN) {
    int w = (blockIdx.x * blockDim.x + threadIdx.x) >> 5;
    if (w >= nN / 2) return;
    int      lane = threadIdx.x & 31;
    int      h    = lane >> 4;                      // half-warp id
    int      c    = lane & 15;                      // float4 chunk / csr slot
    unsigned hm   = h ? 0xFFFF0000u : 0x0000FFFFu;
    int      v    = 2 * w + h;                      // 0-based node

    int2 sd    = __ldg(&seg[v]);                    // {start, deg}
    int  start = sd.x;
    int  p16   = (sd.y + 15) & ~15;

    float4 acc = make_float4(0.f, 0.f, 0.f, 0.f);

    for (int j0 = 0; j0 < p16; j0 += 16) {
        int idx = __ldcs(&csr[start + j0 + c]);     // 16 entries per half-warp
        #pragma unroll
        for (int j = 0; j < 16; j++) {
            int s = __shfl_sync(hm, idx, h * 16 + j);
            float4 vv = __ldg(reinterpret_cast<const float4*>(
                                  x + (size_t)s * DIM) + c);
            acc.x += vv.x; acc.y += vv.y; acc.z += vv.z; acc.w += vv.w;
        }
    }

    float iv = invd[v];
    float4 o = make_float4(acc.x * iv, acc.y * iv, acc.z * iv, acc.w * iv);
    __stwt(&reinterpret_cast<float4*>(om + (size_t)(v + 1) * DIM)[c], o);
}

// ---------------------------------------------------------------------------
// Combine: users get mix GEMM ue=[ms|mt]@W^T+b (fp32, float4-packed smem W).
// Mean reads evict-first (read-once). Writes: g_xs/g_xt dense (default ->
// L2-resident for next layer's gathers; skipped on last layer) and the
// g_embs slice (evict-first; consumed only by pred at the end).
// ---------------------------------------------------------------------------
__global__ void __launch_bounds__(256)
k_combine(const float* __restrict__ mix_w, const float* __restrict__ mix_b,
          int layer, int write_next) {
    // WT4[k2*32 + ln] = { W[ln][2k2], W[ln+32][2k2], W[ln][2k2+1], W[ln+32][2k2+1] }
    __shared__ float4 WT4[64 * 32];    // 32 KB
    __shared__ float  BB[64];

    const float* W = mix_w + (size_t)layer * 64 * 128;
    for (int i = threadIdx.x; i < 64 * 32; i += blockDim.x) {
        int k2 = i >> 5, ln = i & 31;
        WT4[i] = make_float4(W[ln * 128 + 2 * k2],     W[(ln + 32) * 128 + 2 * k2],
                             W[ln * 128 + 2 * k2 + 1], W[(ln + 32) * 128 + 2 * k2 + 1]);
    }
    if (threadIdx.x < 64) BB[threadIdx.x] = mix_b[layer * 64 + threadIdx.x];
    __syncthreads();

    int lane = threadIdx.x & 31;
    int warp = threadIdx.x >> 5;
    int wpb  = blockDim.x >> 5;

    for (int v = blockIdx.x * wpb + warp; v < N_NODES; v += gridDim.x * wpb) {
        size_t base = (size_t)(v + 1) * DIM;

        float ms0 = __ldcs(&g_means[base + lane]);
        float ms1 = __ldcs(&g_means[base + 32 + lane]);
        float mt0 = __ldcs(&g_meant[base + lane]);
        float mt1 = __ldcs(&g_meant[base + 32 + lane]);

        float o0, o1, t0, t1;
        if (v < N_USERS) {
            float a0 = BB[lane], a1 = BB[lane + 32];
            #pragma unroll
            for (int k2 = 0; k2 < 16; k2++) {
                float m0 = __shfl_sync(0xffffffffu, ms0, 2 * k2);
                float m1 = __shfl_sync(0xffffffffu, ms0, 2 * k2 + 1);
                float4 qv = WT4[k2 * 32 + lane];
                a0 += m0 * qv.x + m1 * qv.z;
                a1 += m0 * qv.y + m1 * qv.w;
            }
            #pragma unroll
            for (int k2 = 0; k2 < 16; k2++) {
                float m0 = __shfl_sync(0xffffffffu, ms1, 2 * k2);
                float m1 = __shfl_sync(0xffffffffu, ms1, 2 * k2 + 1);
                float4 qv = WT4[(16 + k2) * 32 + lane];
                a0 += m0 * qv.x + m1 * qv.z;
                a1 += m0 * qv.y + m1 * qv.w;
            }
            #pragma unroll
            for (int k2 = 0; k2 < 16; k2++) {
                float m0 = __shfl_sync(0xffffffffu, mt0, 2 * k2);
                float m1 = __shfl_sync(0xffffffffu, mt0, 2 * k2 + 1);
                float4 qv = WT4[(32 + k2) * 32 + lane];
                a0 += m0 * qv.x + m1 * qv.z;
                a1 += m0 * qv.y + m1 * qv.w;
            }
            #pragma unroll
            for (int k2 = 0; k2 < 16; k2++) {
                float m0 = __shfl_sync(0xffffffffu, mt1, 2 * k2);
                float m1 = __shfl_sync(0xffffffffu, mt1, 2 * k2 + 1);
                float4 qv = WT4[(48 + k2) * 32 + lane];
                a0 += m0 * qv.x + m1 * qv.z;
                a1 += m0 * qv.y + m1 * qv.w;
            }
            o0 = a0; o1 = a1; t0 = a0; t1 = a1;
        } else {
            o0 = ms0; o1 = ms1; t0 = mt0; t1 = mt1;
        }

        if (write_next) {
            g_xs[base + lane]      = o0;            // default: keep in L2
            g_xs[base + 32 + lane] = o1;
            g_xt[base + lane]      = t0;
            g_xt[base + 32 + lane] = t1;
        }
        float* er = g_embs + (size_t)(v + 1) * EMB_COLS + (size_t)(layer + 1) * DIM;
        __stwt(&er[lane],      o0);                 // pred-only: evict-first
        __stwt(&er[lane + 32], o1);
    }
}

// ---------------------------------------------------------------------------
// Prediction head: warp per link, float4 loads (1-based rows, fp32).
// ---------------------------------------------------------------------------
__global__ void k_pred(const int* __restrict__ link,
                       const float* __restrict__ pred_w,
                       const float* __restrict__ pred_b,
                       float* __restrict__ out) {
    __shared__ float4 pw4[128];                       // 512 floats
    for (int i = threadIdx.x; i < 128; i += blockDim.x)
        pw4[i] = reinterpret_cast<const float4*>(pred_w)[i];
    __syncthreads();

    int lane = threadIdx.x & 31;
    int warp = threadIdx.x >> 5;
    int j = blockIdx.x * (blockDim.x >> 5) + warp;
    if (j >= N_LINK) return;

    int u  = __ldg(&link[j]) + 1;
    int it = __ldg(&link[N_LINK + j]) + 1;
    const float4* ue4 = reinterpret_cast<const float4*>(g_embs + (size_t)u  * EMB_COLS);
    const float4* ie4 = reinterpret_cast<const float4*>(g_embs + (size_t)it * EMB_COLS);

    float acc = 0.f;
    #pragma unroll
    for (int r = 0; r < 2; r++) {
        int idx = lane + r * 32;                      // 0..63
        float4 a = __ldg(&ue4[idx]);
        float4 w = pw4[idx];
        acc += a.x * w.x + a.y * w.y + a.z * w.z + a.w * w.w;
        float4 b = __ldg(&ie4[idx]);
        float4 w2 = pw4[64 + idx];
        acc += b.x * w2.x + b.y * w2.y + b.z * w2.z + b.w * w2.w;
    }

    #pragma unroll
    for (int o = 16; o > 0; o >>= 1) acc += __shfl_down_sync(0xffffffffu, acc, o);

    if (lane == 0) {
        float z = acc + pred_b[0];
        z = (z >= 0.f) ? z : 0.01f * z;
        out[j] = 1.f / (1.f + expf(-z));
    }
}

// ---------------------------------------------------------------------------
// Tail: restore the zero state (deg arrays + totals) for the next call.
// (CSR padding is re-zeroed per-call in k_offsets; data slots overwritten.)
// ---------------------------------------------------------------------------
__global__ void k_tail() {
    int stride = gridDim.x * blockDim.x;
    int t0 = blockIdx.x * blockDim.x + threadIdx.x;
    for (int i = t0; i < N_NODES; i += stride) { g_deg_s[i] = 0; g_deg_t[i] = 0; }
    if (t0 == 0) { g_tot_s = 0; g_tot_t = 0; }
}

// ---------------------------------------------------------------------------
// Launch.
// ---------------------------------------------------------------------------
extern "C" void kernel_launch(void* const* d_in, const int* in_sizes, int n_in,
                              void* d_out, int out_size) {
    const int*   sei    = (const int*)  d_in[0];
    const int*   tei    = (const int*)  d_in[1];
    const int*   link   = (const int*)  d_in[2];
    const float* emb    = (const float*)d_in[3];
    const float* mix_w  = (const float*)d_in[4];
    const float* mix_b  = (const float*)d_in[5];
    const float* pred_w = (const float*)d_in[6];
    const float* pred_b = (const float*)d_in[7];
    float*       out    = (float*)d_out;

    const int* s_src = sei;
    const int* s_dst = sei + E_EDGES;
    const int* t_src = tei;
    const int* t_dst = tei + E_EDGES;

    k_hist   <<<(E_EDGES + 255) / 256, 256>>>(s_dst, t_dst);
    k_offsets<<<(N_NODES + 255) / 256, 256>>>(reinterpret_cast<const float4*>(emb));
    k_fill   <<<(E_EDGES + 255) / 256, 256>>>(s_src, s_dst, t_src, t_dst);

    for (int l = 0; l < LAYERS; l++) {
        // source conv: dense g_xs -> g_means
        k_conv<<<(N_NODES / 2 * 32 + 255) / 256, 256>>>(
            g_xs, g_seg_s, g_invdeg_s, g_csr_s, g_means, N_NODES);
        // target conv: layer 0 gathers g_xs (same emb table); else g_xt.
        // Last layer: only user rows are ever consumed.
        const float* xt = (l == 0) ? g_xs : g_xt;
        int          nT = (l == LAYERS - 1) ? N_USERS : N_NODES;
        k_conv<<<(nT / 2 * 32 + 255) / 256, 256>>>(
            xt, g_seg_t, g_invdeg_t, g_csr_t, g_meant, nT);

        k_combine<<<2960, 256>>>(mix_w, mix_b, l, l < LAYERS - 1 ? 1 : 0);
    }

    k_pred<<<(N_LINK + 7) / 8, 256>>>(link, pred_w, pred_b, out);
    k_tail<<<4096, 256>>>();
}

// round 14
// speedup vs baseline: 1.2109x; 1.0174x over previous
#include <cuda_runtime.h>
#include <math.h>

// Problem constants
static constexpr int   N_NODES  = 200000;
static constexpr int   N_USERS  = 100000;
static constexpr int   DIM      = 64;
static constexpr int   LAYERS   = 3;
static constexpr int   E_EDGES  = 3000000;
static constexpr int   N_LINK   = 100000;
static constexpr int   EMB_COLS = (LAYERS + 1) * DIM;     // 256
static constexpr int   ELLW     = 48;                     // ELL row width
static constexpr int   OVF_CAP  = 4096;

// ---------------------------------------------------------------------------
// Scratch. Feature tables have a ZERO GUARD ROW at index 0 (node v -> row v+1).
// Guard rows are never written (zero from .bss forever).
//
// ELL adjacency: g_ell_x[v*48 + p] = src+1 for p < deg(v); slots
// [deg, ceil16(deg)) are zeroed each call by k_prep (conv reads exactly
// ceil16(deg) entries, capped at 48); deeper slots are never read.
// Edges beyond 48 per node (probability ~1e-12, but handled correctly) go
// to an overflow list applied by k_ovf after each conv pair.
// cnt/ovf counters are re-zeroed by k_tail so every call does identical work.
// ---------------------------------------------------------------------------
__device__ int    g_cnt_s[N_NODES],  g_cnt_t[N_NODES];
__device__ int    g_ell_s[(size_t)N_NODES * ELLW];
__device__ int    g_ell_t[(size_t)N_NODES * ELLW];
__device__ int    g_ovfn_s, g_ovfn_t;
__device__ int2   g_ovf_s[OVF_CAP], g_ovf_t[OVF_CAP];     // {dst, src}
__device__ float  g_invdeg_s[N_NODES], g_invdeg_t[N_NODES];
__device__ float  g_means[(size_t)(N_NODES + 1) * DIM];       // +guard
__device__ float  g_meant[(size_t)(N_NODES + 1) * DIM];       // +guard
__device__ float  g_xs   [(size_t)(N_NODES + 1) * DIM];       // dense source gather
__device__ float  g_xt   [(size_t)(N_NODES + 1) * DIM];       // dense target gather
__device__ float  g_embs [(size_t)(N_NODES + 1) * EMB_COLS];  // [emb|x1|x2|x3] (pred)

// ---------------------------------------------------------------------------
// (1) One-pass ELL build for BOTH graphs: slot = atomicAdd(cnt[dst]).
// Replaces histogram + scan + cursor-fill (halves total atomic ops).
// ---------------------------------------------------------------------------
__global__ void k_build(const int* __restrict__ s_src, const int* __restrict__ s_dst,
                        const int* __restrict__ t_src, const int* __restrict__ t_dst) {
    int e = blockIdx.x * blockDim.x + threadIdx.x;
    if (e >= E_EDGES) return;
    {
        int d = s_dst[e], s = s_src[e];
        int p = atomicAdd(&g_cnt_s[d], 1);
        if (p < ELLW) g_ell_s[(size_t)d * ELLW + p] = s + 1;
        else { int o = atomicAdd(&g_ovfn_s, 1); if (o < OVF_CAP) g_ovf_s[o] = make_int2(d, s); }
    }
    {
        int d = t_dst[e], s = t_src[e];
        int p = atomicAdd(&g_cnt_t[d], 1);
        if (p < ELLW) g_ell_t[(size_t)d * ELLW + p] = s + 1;
        else { int o = atomicAdd(&g_ovfn_t, 1); if (o < OVF_CAP) g_ovf_t[o] = make_int2(d, s); }
    }
}

// ---------------------------------------------------------------------------
// (2) Prep: invdeg from counts; zero ELL pad slots [deg, min(ceil16(deg),48));
// copy emb into g_embs column block 0 and the dense layer-0 gather table g_xs.
// ---------------------------------------------------------------------------
__global__ void k_prep(const float4* __restrict__ emb4) {
    int i = blockIdx.x * blockDim.x + threadIdx.x;
    if (i < N_NODES) {
        int ds = g_cnt_s[i], dt = g_cnt_t[i];
        g_invdeg_s[i] = 1.f / fmaxf((float)ds, 1.f);
        g_invdeg_t[i] = 1.f / fmaxf((float)dt, 1.f);
        int ps = min((ds + 15) & ~15, ELLW);
        int pt = min((dt + 15) & ~15, ELLW);
        for (int p = ds; p < ps; p++) g_ell_s[(size_t)i * ELLW + p] = 0;
        for (int p = dt; p < pt; p++) g_ell_t[(size_t)i * ELLW + p] = 0;
    }
    // emb -> g_embs (pred table) and g_xs (dense gather table)
    const long NF4 = (long)N_NODES * (DIM / 4);
    long stride = (long)gridDim.x * blockDim.x;
    for (long j = (long)blockIdx.x * blockDim.x + threadIdx.x; j < NF4; j += stride) {
        long v = j >> 4;
        int  d = (int)(j & 15);
        float4 f = emb4[j];
        reinterpret_cast<float4*>(g_embs)[(v + 1) * (EMB_COLS / 4) + d] = f;
        reinterpret_cast<float4*>(g_xs)[(v + 1) * (DIM / 4) + d] = f;
    }
}

// ---------------------------------------------------------------------------
// (3..) Gather conv: HALF-WARP per node, float4 (LDG.128) lanes, dense fp32
// tables (stride DIM), implicit ELL row start (v*48). Most nodes are one
// branch-free 16-group: 1 ELL load + 16 independent gathers; padding slots
// gather the L1-hot guard row. Writes pre-scaled mean (1-based rows).
// ---------------------------------------------------------------------------
__global__ void __launch_bounds__(256)
k_conv(const float* __restrict__ x,
       const int* __restrict__ cnt, const float* __restrict__ invd,
       const int* __restrict__ ell, float* __restrict__ om, int nN) {
    int w = (blockIdx.x * blockDim.x + threadIdx.x) >> 5;
    if (w >= nN / 2) return;
    int      lane = threadIdx.x & 31;
    int      h    = lane >> 4;                      // half-warp id
    int      c    = lane & 15;                      // float4 chunk / ell slot
    unsigned hm   = h ? 0xFFFF0000u : 0x0000FFFFu;
    int      v    = 2 * w + h;                      // 0-based node

    int d   = __ldg(&cnt[v]);
    int p16 = min((d + 15) & ~15, ELLW);
    const int* row = ell + (size_t)v * ELLW;

    float4 acc = make_float4(0.f, 0.f, 0.f, 0.f);

    for (int j0 = 0; j0 < p16; j0 += 16) {
        int idx = __ldg(&row[j0 + c]);              // 16 entries per half-warp
        #pragma unroll
        for (int j = 0; j < 16; j++) {
            int s = __shfl_sync(hm, idx, h * 16 + j);
            float4 vv = __ldg(reinterpret_cast<const float4*>(
                                  x + (size_t)s * DIM) + c);
            acc.x += vv.x; acc.y += vv.y; acc.z += vv.z; acc.w += vv.w;
        }
    }

    float iv = invd[v];
    float4 o = make_float4(acc.x * iv, acc.y * iv, acc.z * iv, acc.w * iv);
    reinterpret_cast<float4*>(om + (size_t)(v + 1) * DIM)[c] = o;
}

// ---------------------------------------------------------------------------
// Overflow fix-up (runs after each conv pair; lists are empty in practice).
// Adds the contributions of edges beyond ELL capacity into the means.
// ---------------------------------------------------------------------------
__global__ void k_ovf(const float* __restrict__ xs, const float* __restrict__ xt, int nT) {
    int ns = min(g_ovfn_s, OVF_CAP);
    for (int i = threadIdx.x; i < ns; i += blockDim.x) {
        int2 p = g_ovf_s[i];
        float iv = g_invdeg_s[p.x];
        const float* src = xs + (size_t)(p.y + 1) * DIM;
        float* dst = g_means + (size_t)(p.x + 1) * DIM;
        for (int c2 = 0; c2 < DIM; c2++) atomicAdd(&dst[c2], src[c2] * iv);
    }
    int nt = min(g_ovfn_t, OVF_CAP);
    for (int i = threadIdx.x; i < nt; i += blockDim.x) {
        int2 p = g_ovf_t[i];
        if (p.x >= nT) continue;
        float iv = g_invdeg_t[p.x];
        const float* src = xt + (size_t)(p.y + 1) * DIM;
        float* dst = g_meant + (size_t)(p.x + 1) * DIM;
        for (int c2 = 0; c2 < DIM; c2++) atomicAdd(&dst[c2], src[c2] * iv);
    }
}

// ---------------------------------------------------------------------------
// Combine: users get mix GEMM ue=[ms|mt]@W^T+b (fp32, float4-packed smem W).
// Writes dense next-layer gather tables g_xs/g_xt (skipped on last layer)
// and the g_embs slice (pred input).
// ---------------------------------------------------------------------------
__global__ void __launch_bounds__(256)
k_combine(const float* __restrict__ mix_w, const float* __restrict__ mix_b,
          int layer, int write_next) {
    // WT4[k2*32 + ln] = { W[ln][2k2], W[ln+32][2k2], W[ln][2k2+1], W[ln+32][2k2+1] }
    __shared__ float4 WT4[64 * 32];    // 32 KB
    __shared__ float  BB[64];

    const float* W = mix_w + (size_t)layer * 64 * 128;
    for (int i = threadIdx.x; i < 64 * 32; i += blockDim.x) {
        int k2 = i >> 5, ln = i & 31;
        WT4[i] = make_float4(W[ln * 128 + 2 * k2],     W[(ln + 32) * 128 + 2 * k2],
                             W[ln * 128 + 2 * k2 + 1], W[(ln + 32) * 128 + 2 * k2 + 1]);
    }
    if (threadIdx.x < 64) BB[threadIdx.x] = mix_b[layer * 64 + threadIdx.x];
    __syncthreads();

    int lane = threadIdx.x & 31;
    int warp = threadIdx.x >> 5;
    int wpb  = blockDim.x >> 5;

    for (int v = blockIdx.x * wpb + warp; v < N_NODES; v += gridDim.x * wpb) {
        size_t base = (size_t)(v + 1) * DIM;

        float ms0 = g_means[base + lane];
        float ms1 = g_means[base + 32 + lane];
        float mt0 = g_meant[base + lane];
        float mt1 = g_meant[base + 32 + lane];

        float o0, o1, t0, t1;
        if (v < N_USERS) {
            float a0 = BB[lane], a1 = BB[lane + 32];
            #pragma unroll
            for (int k2 = 0; k2 < 16; k2++) {
                float m0 = __shfl_sync(0xffffffffu, ms0, 2 * k2);
                float m1 = __shfl_sync(0xffffffffu, ms0, 2 * k2 + 1);
                float4 qv = WT4[k2 * 32 + lane];
                a0 += m0 * qv.x + m1 * qv.z;
                a1 += m0 * qv.y + m1 * qv.w;
            }
            #pragma unroll
            for (int k2 = 0; k2 < 16; k2++) {
                float m0 = __shfl_sync(0xffffffffu, ms1, 2 * k2);
                float m1 = __shfl_sync(0xffffffffu, ms1, 2 * k2 + 1);
                float4 qv = WT4[(16 + k2) * 32 + lane];
                a0 += m0 * qv.x + m1 * qv.z;
                a1 += m0 * qv.y + m1 * qv.w;
            }
            #pragma unroll
            for (int k2 = 0; k2 < 16; k2++) {
                float m0 = __shfl_sync(0xffffffffu, mt0, 2 * k2);
                float m1 = __shfl_sync(0xffffffffu, mt0, 2 * k2 + 1);
                float4 qv = WT4[(32 + k2) * 32 + lane];
                a0 += m0 * qv.x + m1 * qv.z;
                a1 += m0 * qv.y + m1 * qv.w;
            }
            #pragma unroll
            for (int k2 = 0; k2 < 16; k2++) {
                float m0 = __shfl_sync(0xffffffffu, mt1, 2 * k2);
                float m1 = __shfl_sync(0xffffffffu, mt1, 2 * k2 + 1);
                float4 qv = WT4[(48 + k2) * 32 + lane];
                a0 += m0 * qv.x + m1 * qv.z;
                a1 += m0 * qv.y + m1 * qv.w;
            }
            o0 = a0; o1 = a1; t0 = a0; t1 = a1;
        } else {
            o0 = ms0; o1 = ms1; t0 = mt0; t1 = mt1;
        }

        if (write_next) {
            g_xs[base + lane]      = o0;
            g_xs[base + 32 + lane] = o1;
            g_xt[base + lane]      = t0;
            g_xt[base + 32 + lane] = t1;
        }
        float* er = g_embs + (size_t)(v + 1) * EMB_COLS + (size_t)(layer + 1) * DIM;
        er[lane]      = o0;
        er[lane + 32] = o1;
    }
}

// ---------------------------------------------------------------------------
// Prediction head: warp per link, float4 loads (1-based rows, fp32).
// ---------------------------------------------------------------------------
__global__ void k_pred(const int* __restrict__ link,
                       const float* __restrict__ pred_w,
                       const float* __restrict__ pred_b,
                       float* __restrict__ out) {
    __shared__ float4 pw4[128];                       // 512 floats
    for (int i = threadIdx.x; i < 128; i += blockDim.x)
        pw4[i] = reinterpret_cast<const float4*>(pred_w)[i];
    __syncthreads();

    int lane = threadIdx.x & 31;
    int warp = threadIdx.x >> 5;
    int j = blockIdx.x * (blockDim.x >> 5) + warp;
    if (j >= N_LINK) return;

    int u  = __ldg(&link[j]) + 1;
    int it = __ldg(&link[N_LINK + j]) + 1;
    const float4* ue4 = reinterpret_cast<const float4*>(g_embs + (size_t)u  * EMB_COLS);
    const float4* ie4 = reinterpret_cast<const float4*>(g_embs + (size_t)it * EMB_COLS);

    float acc = 0.f;
    #pragma unroll
    for (int r = 0; r < 2; r++) {
        int idx = lane + r * 32;                      // 0..63
        float4 a = __ldg(&ue4[idx]);
        float4 w = pw4[idx];
        acc += a.x * w.x + a.y * w.y + a.z * w.z + a.w * w.w;
        float4 b = __ldg(&ie4[idx]);
        float4 w2 = pw4[64 + idx];
        acc += b.x * w2.x + b.y * w2.y + b.z * w2.z + b.w * w2.w;
    }

    #pragma unroll
    for (int o = 16; o > 0; o >>= 1) acc += __shfl_down_sync(0xffffffffu, acc, o);

    if (lane == 0) {
        float z = acc + pred_b[0];
        z = (z >= 0.f) ? z : 0.01f * z;
        out[j] = 1.f / (1.f + expf(-z));
    }
}

// ---------------------------------------------------------------------------
// Tail: restore zero state (counts + overflow counters) for the next call.
// ELL data slots are overwritten next call; pad slots re-zeroed in k_prep.
// ---------------------------------------------------------------------------
__global__ void k_tail() {
    int stride = gridDim.x * blockDim.x;
    int t0 = blockIdx.x * blockDim.x + threadIdx.x;
    for (int i = t0; i < N_NODES; i += stride) { g_cnt_s[i] = 0; g_cnt_t[i] = 0; }
    if (t0 == 0) { g_ovfn_s = 0; g_ovfn_t = 0; }
}

// ---------------------------------------------------------------------------
// Launch.
// ---------------------------------------------------------------------------
extern "C" void kernel_launch(void* const* d_in, const int* in_sizes, int n_in,
                              void* d_out, int out_size) {
    const int*   sei    = (const int*)  d_in[0];
    const int*   tei    = (const int*)  d_in[1];
    const int*   link   = (const int*)  d_in[2];
    const float* emb    = (const float*)d_in[3];
    const float* mix_w  = (const float*)d_in[4];
    const float* mix_b  = (const float*)d_in[5];
    const float* pred_w = (const float*)d_in[6];
    const float* pred_b = (const float*)d_in[7];
    float*       out    = (float*)d_out;

    const int* s_src = sei;
    const int* s_dst = sei + E_EDGES;
    const int* t_src = tei;
    const int* t_dst = tei + E_EDGES;

    k_build<<<(E_EDGES + 255) / 256, 256>>>(s_src, s_dst, t_src, t_dst);
    k_prep <<<(N_NODES + 255) / 256, 256>>>(reinterpret_cast<const float4*>(emb));

    for (int l = 0; l < LAYERS; l++) {
        // source conv: dense g_xs -> g_means
        k_conv<<<(N_NODES / 2 * 32 + 255) / 256, 256>>>(
            g_xs, g_cnt_s, g_invdeg_s, g_ell_s, g_means, N_NODES);
        // target conv: layer 0 gathers g_xs (same emb table); else g_xt.
        // Last layer: only user rows are ever consumed.
        const float* xt = (l == 0) ? g_xs : g_xt;
        int          nT = (l == LAYERS - 1) ? N_USERS : N_NODES;
        k_conv<<<(nT / 2 * 32 + 255) / 256, 256>>>(
            xt, g_cnt_t, g_invdeg_t, g_ell_t, g_meant, nT);

        k_ovf<<<1, 256>>>(g_xs, xt, nT);

        k_combine<<<2960, 256>>>(mix_w, mix_b, l, l < LAYERS - 1 ? 1 : 0);
    }

    k_pred<<<(N_LINK + 7) / 8, 256>>>(link, pred_w, pred_b, out);
    k_tail<<<4096, 256>>>();
}